// round 4
// baseline (speedup 1.0000x reference)
#include <cuda_runtime.h>
#include <cuda_bf16.h>
#include <cstdint>
#include <math.h>

// QuantumNet fused kernel, round 4: 4-lanes-per-row direct-LDG GEMV.
// 131072 threads (4 per batch row) -> high occupancy + MLP, no smem tiles.

#define KDIM 512
#define THREADS 128

__global__ __launch_bounds__(THREADS, 6)
void qnet_kernel(const float* __restrict__ x,
                 const float* __restrict__ pre_w,
                 const float* __restrict__ pre_b,
                 const float* __restrict__ u3p,
                 const float* __restrict__ post_w,
                 const float* __restrict__ post_b,
                 float* __restrict__ out, int B)
{
    __shared__ float wts[KDIM * 4];   // [k][q] transposed, 8 KB

    const int tid = threadIdx.x;
    #pragma unroll
    for (int i = tid; i < KDIM * 4; i += THREADS) {
        int q = i >> 9;
        int k = i & (KDIM - 1);
        wts[k * 4 + q] = pre_w[i];
    }
    __syncthreads();

    const int gt  = blockIdx.x * THREADS + tid;
    const int row = gt >> 2;          // batch row
    const int c   = gt & 3;           // K-slice lane (0..3)
    if (row >= B) return;

    const float* xr = x + (size_t)row * KDIM + c * 4;

    // Each lane covers k = kq*16 + c*4 + m (m=0..3), kq = 0..31.
    float a0 = 0.f, a1 = 0.f, a2 = 0.f, a3 = 0.f;
    #pragma unroll
    for (int kq = 0; kq < 32; ++kq) {
        float4 xv = *(const float4*)(xr + kq * 16);
        const int k = kq * 16 + c * 4;
        float4 w0 = *(const float4*)&wts[(k + 0) * 4];
        float4 w1 = *(const float4*)&wts[(k + 1) * 4];
        float4 w2 = *(const float4*)&wts[(k + 2) * 4];
        float4 w3 = *(const float4*)&wts[(k + 3) * 4];
        a0 = fmaf(xv.x, w0.x, a0); a1 = fmaf(xv.x, w0.y, a1);
        a2 = fmaf(xv.x, w0.z, a2); a3 = fmaf(xv.x, w0.w, a3);
        a0 = fmaf(xv.y, w1.x, a0); a1 = fmaf(xv.y, w1.y, a1);
        a2 = fmaf(xv.y, w1.z, a2); a3 = fmaf(xv.y, w1.w, a3);
        a0 = fmaf(xv.z, w2.x, a0); a1 = fmaf(xv.z, w2.y, a1);
        a2 = fmaf(xv.z, w2.z, a2); a3 = fmaf(xv.z, w2.w, a3);
        a0 = fmaf(xv.w, w3.x, a0); a1 = fmaf(xv.w, w3.y, a1);
        a2 = fmaf(xv.w, w3.z, a2); a3 = fmaf(xv.w, w3.w, a3);
    }

    // Reduce across the 4 lanes of this row (lanes r*4+0..3 within warp).
    a0 += __shfl_xor_sync(0xFFFFFFFFu, a0, 1); a0 += __shfl_xor_sync(0xFFFFFFFFu, a0, 2);
    a1 += __shfl_xor_sync(0xFFFFFFFFu, a1, 1); a1 += __shfl_xor_sync(0xFFFFFFFFu, a1, 2);
    a2 += __shfl_xor_sync(0xFFFFFFFFu, a2, 1); a2 += __shfl_xor_sync(0xFFFFFFFFu, a2, 2);
    a3 += __shfl_xor_sync(0xFFFFFFFFu, a3, 1); a3 += __shfl_xor_sync(0xFFFFFFFFu, a3, 2);

    if (c != 0) return;   // one epilogue thread per row

    float pre[4];
    pre[0] = a0 + pre_b[0];
    pre[1] = a1 + pre_b[1];
    pre[2] = a2 + pre_b[2];
    pre[3] = a3 + pre_b[3];

    // Per-qubit state after H, RY(atan t), RZ(atan t^2):
    //   alpha = (c-s)/sqrt2 e^{-i rz/2}, beta = (c+s)/sqrt2 e^{+i rz/2}
    float aR[4], aI[4], bR[4], bI[4];
    const float HALF_PI = 1.5707963267948966f;
    const float INV_SQRT2 = 0.7071067811865476f;
    #pragma unroll
    for (int q = 0; q < 4; ++q) {
        float t  = tanhf(pre[q] * 0.1f) * HALF_PI;
        float cr = rsqrtf(fmaf(t, t, 1.f));
        float sr = t * cr;
        float c2 = sqrtf(0.5f * (1.f + cr));
        float s2 = 0.5f * sr * __fdividef(1.f, c2);
        float u  = t * t;
        float cz = rsqrtf(fmaf(u, u, 1.f));
        float szf = u * cz;
        float ch = sqrtf(0.5f * (1.f + cz));
        float sh = 0.5f * szf * __fdividef(1.f, ch);
        float Aa = (c2 - s2) * INV_SQRT2;
        float Bb = (c2 + s2) * INV_SQRT2;
        aR[q] = Aa * ch;  aI[q] = -Aa * sh;
        bR[q] = Bb * ch;  bI[q] =  Bb * sh;
    }

    float tR[4], tI[4], uR[4], uI[4];
    #pragma unroll
    for (int h = 0; h < 4; ++h) {
        int j0 = h >> 1, j1 = h & 1;
        float r0 = j0 ? bR[0] : aR[0], i0 = j0 ? bI[0] : aI[0];
        float r1 = j1 ? bR[1] : aR[1], i1 = j1 ? bI[1] : aI[1];
        tR[h] = r0 * r1 - i0 * i1;
        tI[h] = r0 * i1 + i0 * r1;
        float r2 = j0 ? bR[2] : aR[2], i2 = j0 ? bI[2] : aI[2];
        float r3 = j1 ? bR[3] : aR[3], i3 = j1 ? bI[3] : aI[3];
        uR[h] = r2 * r3 - i2 * i3;
        uI[h] = r2 * i3 + i2 * r3;
    }

    // Post-CNOT state via compile-time GF(2) permutation
    float AR[16], AI[16], NR[16];
    #pragma unroll
    for (int i = 0; i < 16; ++i) {
        int a_ = (i >> 3) & 1, b_ = (i >> 2) & 1, c_ = (i >> 1) & 1, d_ = i & 1;
        int s  = ((a_ ^ b_ ^ c_) << 3) | ((a_ ^ c_ ^ d_) << 2)
               | ((a_ ^ b_ ^ d_) << 1) | (a_ ^ b_);
        int hi = s >> 2, lo = s & 3;
        AR[i] = tR[hi] * uR[lo] - tI[hi] * uI[lo];
        AI[i] = tR[hi] * uI[lo] + tI[hi] * uR[lo];
        NR[i] = AR[i] * AR[i] + AI[i] * AI[i];
    }

    // U3 folded into M_q = U3^dag Z U3
    float ct4[4], mr4[4], mi4[4];
    #pragma unroll
    for (int q = 0; q < 4; ++q) {
        float th = u3p[q * 3 + 0];
        float la = u3p[q * 3 + 2];
        float st_, ct_, sl_, cl_;
        __sincosf(th, &st_, &ct_);
        __sincosf(la, &sl_, &cl_);
        ct4[q] = ct_;
        mr4[q] = -st_ * cl_;
        mi4[q] = -st_ * sl_;
    }

    float E[4];
    #pragma unroll
    for (int q = 0; q < 4; ++q) {
        const int p = 3 - q;
        float Sn = 0.f, Szr = 0.f, Szi = 0.f;
        #pragma unroll
        for (int m = 0; m < 8; ++m) {
            int lowmask = (1 << p) - 1;
            int i0 = ((m & ~lowmask) << 1) | (m & lowmask);
            int i1 = i0 | (1 << p);
            Sn  += NR[i0] - NR[i1];
            Szr += AR[i0] * AR[i1] + AI[i0] * AI[i1];
            Szi += AR[i0] * AI[i1] - AI[i0] * AR[i1];
        }
        E[q] = ct4[q] * Sn + 2.f * (mr4[q] * Szr - mi4[q] * Szi);
    }

    float o0 = post_b[0], o1 = post_b[1];
    #pragma unroll
    for (int q = 0; q < 4; ++q) {
        o0 = fmaf(post_w[q],     E[q], o0);
        o1 = fmaf(post_w[4 + q], E[q], o1);
    }
    float2 res; res.x = o0; res.y = o1;
    ((float2*)out)[row] = res;
}

extern "C" void kernel_launch(void* const* d_in, const int* in_sizes, int n_in,
                              void* d_out, int out_size) {
    const float* x      = (const float*)d_in[0];
    const float* pre_w  = (const float*)d_in[1];
    const float* pre_b  = (const float*)d_in[2];
    const float* u3p    = (const float*)d_in[3];
    const float* post_w = (const float*)d_in[4];
    const float* post_b = (const float*)d_in[5];
    float* out = (float*)d_out;

    int B = in_sizes[0] / KDIM;
    long long total = (long long)B * 4;
    int grid = (int)((total + THREADS - 1) / THREADS);
    qnet_kernel<<<grid, THREADS>>>(x, pre_w, pre_b, u3p, post_w, post_b, out, B);
}